// round 1
// baseline (speedup 1.0000x reference)
#include <cuda_runtime.h>
#include <cuda_bf16.h>
#include <cstdint>

// Problem constants: x (1024,64), D (64,256), w (256). Output (1024,2) fp32.
#define NN 1024
#define MM 256
#define DN 64
#define LAMBD 0.2f
#define MAXIT 1400
#define GROUPS 8

// ---------------- device scratch (no allocations allowed) ----------------
__device__ float    g_G[MM * MM];      // fp32 Gram D^T D, row-major
__device__ unsigned g_Gp[MM * 128];    // packed bf16x2: Gp[k*128+t] = (G[k][t], G[k][t+128])
__device__ float    g_A64[DN * DN];    // D D^T
__device__ float    g_eta[2];          // eta, thr = LAMBD*eta
__device__ float    g_B[NN * MM];      // (D^T x_i)_j  at [i*256+j], fp32
__device__ float    g_Z[NN * MM];      // ISTA result z per sample

// ---------------- K1: G = D^T D ----------------
__global__ void gram_kernel(const float* __restrict__ D) {
    __shared__ float Dj[DN];
    int j = blockIdx.x, k = threadIdx.x;
    if (k < DN) Dj[k] = D[k * MM + j];
    __syncthreads();
    float acc = 0.f;
#pragma unroll 8
    for (int n = 0; n < DN; ++n) acc = fmaf(Dj[n], D[n * MM + k], acc);
    g_G[j * MM + k] = acc;
}

// ---------------- K1b: A = D D^T (64x64) ----------------
__global__ void ddt_kernel(const float* __restrict__ D) {
    __shared__ float Di[MM];
    int i = blockIdx.x, j = threadIdx.x;
    for (int t = j; t < MM; t += DN) Di[t] = D[i * MM + t];
    __syncthreads();
    float acc = 0.f;
#pragma unroll 8
    for (int m = 0; m < MM; ++m) acc = fmaf(Di[m], D[j * MM + m], acc);
    g_A64[i * DN + j] = acc;
}

// ---------------- K1c: pack G -> bf16x2 ----------------
__global__ void pack_kernel() {
    int t = blockIdx.x * 256 + threadIdx.x;       // 0..32767
    int k = t >> 7, lt = t & 127;
    __nv_bfloat16 b0 = __float2bfloat16(g_G[k * MM + lt]);
    __nv_bfloat16 b1 = __float2bfloat16(g_G[k * MM + 128 + lt]);
    unsigned u0 = (unsigned)__bfloat16_as_ushort(b0);
    unsigned u1 = (unsigned)__bfloat16_as_ushort(b1);
    g_Gp[t] = u0 | (u1 << 16);
}

// ---------------- K2: power iteration for eta = 1/lambda_max ----------------
__device__ __forceinline__ float red64(float v, float* sred, int tid) {
#pragma unroll
    for (int o = 16; o; o >>= 1) v += __shfl_down_sync(0xffffffffu, v, o);
    if ((tid & 31) == 0) sred[tid >> 5] = v;
    __syncthreads();
    float r = sred[0] + sred[1];
    __syncthreads();
    return r;
}

__global__ void power_kernel() {
    __shared__ float As[DN * DN];
    __shared__ float vs[DN];
    __shared__ float sred[2];
    int j = threadIdx.x;
    for (int t = j; t < DN * DN; t += DN) As[t] = g_A64[t];
    vs[j] = 1.0f;
    __syncthreads();
    float acc = 0.f;
    for (int it = 0; it < 300; ++it) {
        acc = 0.f;
#pragma unroll 8
        for (int k = 0; k < DN; ++k) acc = fmaf(As[k * DN + j], vs[k], acc);
        if ((it & 7) == 7) {
            float ss = red64(acc * acc, sred, j);
            acc *= rsqrtf(ss);
        }
        __syncthreads();
        vs[j] = acc;
        __syncthreads();
    }
    acc = 0.f;
#pragma unroll 8
    for (int k = 0; k < DN; ++k) acc = fmaf(As[k * DN + j], vs[k], acc);
    float vw = red64(acc * vs[j], sred, j);
    float vv = red64(vs[j] * vs[j], sred, j);
    if (j == 0) {
        float eta = vv / vw;             // 1/lambda_max (Rayleigh)
        g_eta[0] = eta;
        g_eta[1] = LAMBD * eta;
    }
}

// ---------------- K3: B = D^T x, fp32 ----------------
__global__ void btx_kernel(const float* __restrict__ x, const float* __restrict__ D) {
    __shared__ float xs[DN];
    int i = blockIdx.x, j = threadIdx.x;
    if (j < DN) xs[j] = x[i * DN + j];
    __syncthreads();
    float acc = 0.f;
#pragma unroll 8
    for (int n = 0; n < DN; ++n) acc = fmaf(xs[n], D[n * MM + j], acc);
    g_B[i * MM + j] = acc;
}

// ---------------- K4: ISTA, bf16 G in SMEM, sparse matvec, early exit ----------------
// 128 blocks x 1024 threads; 8 independent 128-thread groups (1 sample each).
// Per-group SMEM slot layout (u32): [0..255] zbuf0, [256..511] zbuf1,
// [512..519] mask0, [520..527] mask1, [528..531] flags0, [532..535] flags1, pad->544
#define SLOT_U32 544
#define ISTA_SMEM ((32768 + GROUPS * SLOT_U32) * 4)

__device__ __forceinline__ void bar_group(int g) {
    asm volatile("bar.sync %0, %1;" :: "r"(g + 1), "r"(128) : "memory");
}

__global__ void __launch_bounds__(1024, 1) ista_kernel() {
    extern __shared__ unsigned smem_u[];
    unsigned* Gs = smem_u;  // 32768 u32 = bf16x2 G columns

    // cooperative load of packed G
    {
        const uint4* src = (const uint4*)g_Gp;
        uint4* dst = (uint4*)Gs;
        for (int t = threadIdx.x; t < (MM * 128) / 4; t += 1024) dst[t] = src[t];
    }
    __syncthreads();

    int g = threadIdx.x >> 7;
    int lt = threadIdx.x & 127;
    int wg = lt >> 5;
    int lane = lt & 31;
    int s = blockIdx.x * GROUPS + g;

    unsigned* base = smem_u + 32768 + g * SLOT_U32;
    float* zbuf0 = (float*)base;
    float* zbuf1 = (float*)(base + 256);
    unsigned* mask0 = base + 512;
    unsigned* mask1 = base + 520;
    unsigned* flags0 = base + 528;
    unsigned* flags1 = base + 532;

    float eta = g_eta[0];
    float thr = g_eta[1];

    float c_lo = eta * g_B[s * MM + lt];
    float c_hi = eta * g_B[s * MM + 128 + lt];

    // z0 = softshrink(c, thr)
    float a0 = fabsf(c_lo) - thr;
    float a1 = fabsf(c_hi) - thr;
    float zlo = a0 > 0.f ? copysignf(a0, c_lo) : 0.f;
    float zhi = a1 > 0.f ? copysignf(a1, c_hi) : 0.f;

    zbuf0[lt] = zlo;
    zbuf0[128 + lt] = zhi;
    unsigned blo = __ballot_sync(0xffffffffu, zlo != 0.f);
    unsigned bhi = __ballot_sync(0xffffffffu, zhi != 0.f);
    if (lane == 0) { mask0[wg] = blo; mask0[4 + wg] = bhi; }
    bar_group(g);

    for (int t = 0; t < MAXIT; ++t) {
        int rb = t & 1;
        const float* zr = rb ? zbuf1 : zbuf0;
        float* zw = rb ? zbuf0 : zbuf1;
        unsigned* mr = rb ? mask1 : mask0;
        unsigned* mw = rb ? mask0 : mask1;
        unsigned* fw = rb ? flags0 : flags1;

        float vlo = 0.f, vhi = 0.f;
#pragma unroll
        for (int w = 0; w < 8; ++w) {
            unsigned bits = mr[w];
            int kb = w << 5;
            while (bits) {
                int b = __ffs((int)bits) - 1;
                bits &= bits - 1;
                int k = kb + b;
                float zk = zr[k];
                unsigned gw = Gs[(k << 7) + lt];
                vlo = fmaf(__uint_as_float(gw << 16), zk, vlo);
                vhi = fmaf(__uint_as_float(gw & 0xffff0000u), zk, vhi);
            }
        }

        float ulo = fmaf(-eta, vlo, zlo) + c_lo;
        float uhi = fmaf(-eta, vhi, zhi) + c_hi;
        float alo = fabsf(ulo) - thr;
        float ahi = fabsf(uhi) - thr;
        float nlo = alo > 0.f ? copysignf(alo, ulo) : 0.f;
        float nhi = ahi > 0.f ? copysignf(ahi, uhi) : 0.f;

        bool chg = (fabsf(nlo - zlo) > 1e-7f) || (fabsf(nhi - zhi) > 1e-7f);
        zlo = nlo; zhi = nhi;

        zw[lt] = zlo;
        zw[128 + lt] = zhi;
        unsigned b0 = __ballot_sync(0xffffffffu, zlo != 0.f);
        unsigned b1 = __ballot_sync(0xffffffffu, zhi != 0.f);
        unsigned anych = __ballot_sync(0xffffffffu, chg);
        if (lane == 0) { mw[wg] = b0; mw[4 + wg] = b1; fw[wg] = anych; }
        bar_group(g);
        if ((fw[0] | fw[1] | fw[2] | fw[3]) == 0) break;
    }

    g_Z[s * MM + lt] = zlo;
    g_Z[s * MM + 128 + lt] = zhi;
}

// ---------------- K5: support refinement (Cholesky solve) + output ----------------
#define MAXS 128
#define REF_SMEM ((MAXS * MAXS + MAXS + MM + MAXS + 128) * 4)

__global__ void __launch_bounds__(128) refine_kernel(const float* __restrict__ w,
                                                     float* __restrict__ out) {
    extern __shared__ float sm[];
    float* A = sm;                         // s*s, leading dim s
    float* vec = sm + MAXS * MAXS;         // MAXS
    float* zs = vec + MAXS;                // 256
    int* idx = (int*)(zs + MM);            // MAXS
    float* red = (float*)(idx + MAXS);     // 128
    __shared__ int cnt_s;

    int i = blockIdx.x, tid = threadIdx.x;
    zs[tid] = g_Z[i * MM + tid];
    zs[128 + tid] = g_Z[i * MM + 128 + tid];
    __syncthreads();

    if (tid == 0) {
        int c = 0;
        for (int j = 0; j < MM; ++j)
            if (zs[j] != 0.f && c < MAXS) idx[c++] = j;
        cnt_s = c;
    }
    __syncthreads();
    int s = cnt_s;

    if (s == 0) {
        if (tid == 0) { out[2 * i] = 0.f; out[2 * i + 1] = -0.0f; }
        return;
    }

    for (int t = tid; t < s * s; t += 128) {
        int r = t / s, q = t - r * s;
        A[r * s + q] = g_G[idx[r] * MM + idx[q]];
    }
    if (tid < s) {
        float zv = zs[idx[tid]];
        float sg = zv > 0.f ? 1.f : -1.f;
        vec[tid] = g_B[i * MM + idx[tid]] - LAMBD * sg;
    }
    __syncthreads();

    // Cholesky: A = L L^T, L in lower triangle
    for (int k = 0; k < s; ++k) {
        if (tid == 0) A[k * s + k] = sqrtf(fmaxf(A[k * s + k], 1e-30f));
        __syncthreads();
        float piv = A[k * s + k];
        for (int r = k + 1 + tid; r < s; r += 128) A[r * s + k] /= piv;
        __syncthreads();
        for (int r = k + 1 + tid; r < s; r += 128) {
            float lrk = A[r * s + k];
            for (int q = k + 1; q <= r; ++q) A[r * s + q] -= lrk * A[q * s + k];
        }
        __syncthreads();
    }
    // forward: vec := L^{-1} vec
    for (int k = 0; k < s; ++k) {
        if (tid == 0) vec[k] /= A[k * s + k];
        __syncthreads();
        float vk = vec[k];
        for (int r = k + 1 + tid; r < s; r += 128) vec[r] -= A[r * s + k] * vk;
        __syncthreads();
    }
    // backward: vec := L^{-T} vec
    for (int k = s - 1; k >= 0; --k) {
        if (tid == 0) vec[k] /= A[k * s + k];
        __syncthreads();
        float vk = vec[k];
        for (int r = tid; r < k; r += 128) vec[r] -= A[k * s + r] * vk;
        __syncthreads();
    }
    // y = sum_j w[S_j] * alpha_j
    float p = 0.f;
    for (int t = tid; t < s; t += 128) p += w[idx[t]] * vec[t];
    red[tid] = p;
    __syncthreads();
    for (int o = 64; o; o >>= 1) {
        if (tid < o) red[tid] += red[tid + o];
        __syncthreads();
    }
    if (tid == 0) {
        float y = red[0];
        out[2 * i] = y;
        out[2 * i + 1] = -y;
    }
}

// ---------------- launch ----------------
extern "C" void kernel_launch(void* const* d_in, const int* in_sizes, int n_in,
                              void* d_out, int out_size) {
    const float* x = (const float*)d_in[0];   // (1024, 64)
    const float* D = (const float*)d_in[1];   // (64, 256)
    const float* w = (const float*)d_in[2];   // (256,)
    float* out = (float*)d_out;               // (1024, 2)

    cudaFuncSetAttribute(ista_kernel, cudaFuncAttributeMaxDynamicSharedMemorySize, ISTA_SMEM);
    cudaFuncSetAttribute(refine_kernel, cudaFuncAttributeMaxDynamicSharedMemorySize, REF_SMEM);

    gram_kernel<<<256, 256>>>(D);
    ddt_kernel<<<64, 64>>>(D);
    pack_kernel<<<128, 256>>>();
    power_kernel<<<1, 64>>>();
    btx_kernel<<<1024, 256>>>(x, D);
    ista_kernel<<<128, 1024, ISTA_SMEM>>>();
    refine_kernel<<<1024, 128, REF_SMEM>>>(w, out);
}

// round 2
// speedup vs baseline: 6.7997x; 6.7997x over previous
#include <cuda_runtime.h>
#include <cuda_bf16.h>
#include <cstdint>

// Problem: x (1024,64), D (64,256), w (256). Output (1024,2) fp32.
#define NN 1024
#define MM 256
#define DN 64
#define LAMBD 0.2f
#define CHG_EPS 4e-7f
#define MAX_SWEEPS 64

// ---------------- device scratch ----------------
__device__ float    g_G[MM * MM];      // fp32 Gram D^T D, row-major
__device__ unsigned g_Gp[MM * 128];    // packed bf16x2: word[j*128+t] = (G[j][t], G[j][t+128])
__device__ float    g_B[NN * MM];      // b_i = D^T x_i, fp32
__device__ float    g_Z[NN * MM];      // CD result z per sample

// ---------------- K1: G = D^T D ----------------
__global__ void gram_kernel(const float* __restrict__ D) {
    __shared__ float Dj[DN];
    int j = blockIdx.x, k = threadIdx.x;
    if (k < DN) Dj[k] = D[k * MM + j];
    __syncthreads();
    float acc = 0.f;
#pragma unroll 8
    for (int n = 0; n < DN; ++n) acc = fmaf(Dj[n], D[n * MM + k], acc);
    g_G[j * MM + k] = acc;
}

// ---------------- K2: pack G -> bf16x2 ----------------
__global__ void pack_kernel() {
    int t = blockIdx.x * 256 + threadIdx.x;       // 0..32767
    int j = t >> 7, lt = t & 127;
    __nv_bfloat16 b0 = __float2bfloat16(g_G[j * MM + lt]);
    __nv_bfloat16 b1 = __float2bfloat16(g_G[j * MM + 128 + lt]);
    unsigned u0 = (unsigned)__bfloat16_as_ushort(b0);
    unsigned u1 = (unsigned)__bfloat16_as_ushort(b1);
    g_Gp[t] = u0 | (u1 << 16);
}

// ---------------- K3: B = D^T x ----------------
__global__ void btx_kernel(const float* __restrict__ x, const float* __restrict__ D) {
    __shared__ float xs[DN];
    int i = blockIdx.x, j = threadIdx.x;
    if (j < DN) xs[j] = x[i * DN + j];
    __syncthreads();
    float acc = 0.f;
#pragma unroll 8
    for (int n = 0; n < DN; ++n) acc = fmaf(xs[n], D[n * MM + j], acc);
    g_B[i * MM + j] = acc;
}

// ---------------- K4: coordinate descent, warp per sample ----------------
// Lane l owns coords {h*128 + a*32 + l : h in 0..1, a in 0..3}, register slot ai = h*4+a.
// u = b - G z maintained in registers; G_jj = 1 (unit-norm atoms) so z_j <- S_lambda(u_j + z_j).
// Batch trick: all 32 lanes of a (h,a) batch evaluate candidates at once; changed coords are
// applied strictly sequentially via ballot+ffs, preserving exact CD semantics.
#define CD_SMEM (MM * 128 * 4)

__global__ void __launch_bounds__(256, 1) cd_kernel() {
    extern __shared__ unsigned Gs[];  // 32768 words = bf16x2 G rows
    {
        const uint4* src = (const uint4*)g_Gp;
        uint4* dst = (uint4*)Gs;
        for (int t = threadIdx.x; t < (MM * 128) / 4; t += 256) dst[t] = src[t];
    }
    __syncthreads();

    int warp = threadIdx.x >> 5, lane = threadIdx.x & 31;
    int s = blockIdx.x * 8 + warp;

    float uu[8], zz[8];
#pragma unroll
    for (int ai = 0; ai < 8; ++ai) {
        int j = ((ai >> 2) << 7) + ((ai & 3) << 5) + lane;
        uu[ai] = g_B[s * MM + j];
        zz[ai] = 0.f;
    }

    bool refreshed = false;
    for (int sweep = 0; sweep < MAX_SWEEPS; ++sweep) {
        unsigned any = 0;
#pragma unroll
        for (int ai = 0; ai < 8; ++ai) {
            int jbase = ((ai >> 2) << 7) + ((ai & 3) << 5);
            unsigned rem = 0xffffffffu;
            while (true) {
                float c = uu[ai] + zz[ai];
                float ab = fabsf(c) - LAMBD;
                float cand = ab > 0.f ? copysignf(ab, c) : 0.f;
                float dzl = cand - zz[ai];
                bool chgd = fabsf(dzl) > CHG_EPS;
                unsigned chg = __ballot_sync(0xffffffffu, chgd) & rem;
                if (!chg) break;
                any = 1;
                int l0 = __ffs(chg) - 1;
                rem &= ~(1u << l0);
                float dz = __shfl_sync(0xffffffffu, dzl, l0);
                if (lane == l0) zz[ai] = cand;
                int j = jbase + l0;
                const unsigned* grow = Gs + (j << 7) + lane;
#pragma unroll
                for (int b = 0; b < 4; ++b) {
                    unsigned gw = grow[b << 5];
                    uu[b]     = fmaf(__uint_as_float(gw << 16),          -dz, uu[b]);
                    uu[b + 4] = fmaf(__uint_as_float(gw & 0xffff0000u), -dz, uu[b + 4]);
                }
            }
        }
        if (!any) {
            if (refreshed) break;
            // fp32 refresh of u = b - G z (kills accumulated bf16 drift before final decisions)
#pragma unroll
            for (int ai = 0; ai < 8; ++ai) {
                int j = ((ai >> 2) << 7) + ((ai & 3) << 5) + lane;
                uu[ai] = g_B[s * MM + j];
            }
#pragma unroll
            for (int ai = 0; ai < 8; ++ai) {
                int jbase = ((ai >> 2) << 7) + ((ai & 3) << 5);
                unsigned sup = __ballot_sync(0xffffffffu, zz[ai] != 0.f);
                while (sup) {
                    int l0 = __ffs(sup) - 1;
                    sup &= sup - 1;
                    float zk = __shfl_sync(0xffffffffu, zz[ai], l0);
                    const float* gr = g_G + (jbase + l0) * MM + lane;
#pragma unroll
                    for (int b = 0; b < 4; ++b) {
                        uu[b]     = fmaf(gr[(b << 5)],       -zk, uu[b]);
                        uu[b + 4] = fmaf(gr[(b << 5) + 128], -zk, uu[b + 4]);
                    }
                }
            }
            refreshed = true;
        }
    }

#pragma unroll
    for (int ai = 0; ai < 8; ++ai) {
        int j = ((ai >> 2) << 7) + ((ai & 3) << 5) + lane;
        g_Z[s * MM + j] = zz[ai];
    }
}

// ---------------- K5: support refinement (fp32 Cholesky) + output ----------------
#define MAXS 72
#define REF_SMEM ((MAXS * MAXS + MAXS + MM + MAXS + 128) * 4)

__global__ void __launch_bounds__(128) refine_kernel(const float* __restrict__ w,
                                                     float* __restrict__ out) {
    extern __shared__ float sm[];
    float* A = sm;                         // s*s, leading dim s
    float* vec = sm + MAXS * MAXS;         // MAXS
    float* zs = vec + MAXS;                // 256
    int* idx = (int*)(zs + MM);            // MAXS
    float* red = (float*)(idx + MAXS);     // 128
    __shared__ int cnt_s;

    int i = blockIdx.x, tid = threadIdx.x;
    zs[tid] = g_Z[i * MM + tid];
    zs[128 + tid] = g_Z[i * MM + 128 + tid];
    __syncthreads();

    if (tid == 0) {
        int c = 0;
        for (int j = 0; j < MM; ++j)
            if (zs[j] != 0.f && c < MAXS) idx[c++] = j;
        cnt_s = c;
    }
    __syncthreads();
    int s = cnt_s;

    if (s == 0) {
        if (tid == 0) { out[2 * i] = 0.f; out[2 * i + 1] = -0.0f; }
        return;
    }

    for (int t = tid; t < s * s; t += 128) {
        int r = t / s, q = t - r * s;
        A[r * s + q] = g_G[idx[r] * MM + idx[q]];
    }
    if (tid < s) {
        float zv = zs[idx[tid]];
        float sg = zv > 0.f ? 1.f : -1.f;
        vec[tid] = g_B[i * MM + idx[tid]] - LAMBD * sg;
    }
    __syncthreads();

    // Cholesky: A = L L^T (lower triangle)
    for (int k = 0; k < s; ++k) {
        if (tid == 0) A[k * s + k] = sqrtf(fmaxf(A[k * s + k], 1e-30f));
        __syncthreads();
        float piv = A[k * s + k];
        for (int r = k + 1 + tid; r < s; r += 128) A[r * s + k] /= piv;
        __syncthreads();
        for (int r = k + 1 + tid; r < s; r += 128) {
            float lrk = A[r * s + k];
            for (int q = k + 1; q <= r; ++q) A[r * s + q] -= lrk * A[q * s + k];
        }
        __syncthreads();
    }
    // forward solve
    for (int k = 0; k < s; ++k) {
        if (tid == 0) vec[k] /= A[k * s + k];
        __syncthreads();
        float vk = vec[k];
        for (int r = k + 1 + tid; r < s; r += 128) vec[r] -= A[r * s + k] * vk;
        __syncthreads();
    }
    // backward solve
    for (int k = s - 1; k >= 0; --k) {
        if (tid == 0) vec[k] /= A[k * s + k];
        __syncthreads();
        float vk = vec[k];
        for (int r = tid; r < k; r += 128) vec[r] -= A[k * s + r] * vk;
        __syncthreads();
    }
    // y = w_S . alpha_S
    float p = 0.f;
    for (int t = tid; t < s; t += 128) p += w[idx[t]] * vec[t];
    red[tid] = p;
    __syncthreads();
    for (int o = 64; o; o >>= 1) {
        if (tid < o) red[tid] += red[tid + o];
        __syncthreads();
    }
    if (tid == 0) {
        float y = red[0];
        out[2 * i] = y;
        out[2 * i + 1] = -y;
    }
}

// ---------------- launch ----------------
extern "C" void kernel_launch(void* const* d_in, const int* in_sizes, int n_in,
                              void* d_out, int out_size) {
    const float* x = (const float*)d_in[0];   // (1024, 64)
    const float* D = (const float*)d_in[1];   // (64, 256)
    const float* w = (const float*)d_in[2];   // (256,)
    float* out = (float*)d_out;               // (1024, 2)

    cudaFuncSetAttribute(cd_kernel, cudaFuncAttributeMaxDynamicSharedMemorySize, CD_SMEM);
    cudaFuncSetAttribute(refine_kernel, cudaFuncAttributeMaxDynamicSharedMemorySize, REF_SMEM);

    gram_kernel<<<256, 256>>>(D);
    pack_kernel<<<128, 256>>>();
    btx_kernel<<<1024, 256>>>(x, D);
    cd_kernel<<<128, 256, CD_SMEM>>>();
    refine_kernel<<<1024, 128, REF_SMEM>>>(w, out);
}